// round 14
// baseline (speedup 1.0000x reference)
#include <cuda_runtime.h>
#include <cuda_bf16.h>
#include <cuda_fp16.h>
#include <math.h>
#include <stdint.h>

#define BATCH 2
#define HEADS 8
#define NQ 4096
#define NK 4096
#define DMODEL 512
#define DHEAD 64
#define BHX (BATCH * HEADS)
#define MROWS (BATCH * NQ)

#define XN ((size_t)MROWS * DMODEL)
#define WN ((size_t)DMODEL * DMODEL)

// log2(e)/8 folded into Q so p = 2^(q'.k)
#define QSCALE 0.18033688011112042f
#define ONESH2 0x3C003C00u             // fp16x2 {1,1}

// ---------------------------------------------------------------------------
// Scratch (__device__ globals)
// ---------------------------------------------------------------------------
__device__ __half g_q16[(size_t)BHX * NQ * DHEAD];
__device__ __half g_k16[(size_t)BHX * NK * DHEAD];
__device__ __half g_v16[(size_t)BHX * NK * DHEAD];
__device__ __half g_x3[3 * XN];        // X inputs, single fp16
__device__ __half g_w4h[4 * WN];       // W fp16 hi
__device__ __half g_w4l[4 * WN];       // W fp16 lo
__device__ __half g_a16[XN];           // att, single fp16

// ---------------------------------------------------------------------------
// PTX helpers
// ---------------------------------------------------------------------------
__device__ __forceinline__ uint32_t smem_u32(const void* p) {
    uint32_t a;
    asm("{ .reg .u64 t; cvta.to.shared.u64 t, %1; cvt.u32.u64 %0, t; }"
        : "=r"(a) : "l"(p));
    return a;
}
#define SW128(o) ((o) ^ (((o) >> 3) & 0x70))

__device__ __forceinline__ void cp16(uint32_t dst, const void* src) {
    asm volatile("cp.async.cg.shared.global [%0], [%1], 16;"
                 :: "r"(dst), "l"(src) : "memory");
}
#define CP_COMMIT() asm volatile("cp.async.commit_group;" ::: "memory")
#define CP_WAIT(N)  asm volatile("cp.async.wait_group %0;" :: "n"(N) : "memory")

__device__ __forceinline__ void ldsm4(uint32_t* r, uint32_t a) {
    asm volatile("ldmatrix.sync.aligned.m8n8.x4.shared.b16 {%0,%1,%2,%3}, [%4];"
                 : "=r"(r[0]), "=r"(r[1]), "=r"(r[2]), "=r"(r[3]) : "r"(a));
}
__device__ __forceinline__ void ldsm4t(uint32_t* r, uint32_t a) {
    asm volatile("ldmatrix.sync.aligned.m8n8.x4.trans.shared.b16 {%0,%1,%2,%3}, [%4];"
                 : "=r"(r[0]), "=r"(r[1]), "=r"(r[2]), "=r"(r[3]) : "r"(a));
}
__device__ __forceinline__ void mma_f16(float* c, const uint32_t* a,
                                        uint32_t b0, uint32_t b1) {
    asm volatile(
        "mma.sync.aligned.m16n8k16.row.col.f32.f16.f16.f32 "
        "{%0,%1,%2,%3}, {%4,%5,%6,%7}, {%8,%9}, {%0,%1,%2,%3};"
        : "+f"(c[0]), "+f"(c[1]), "+f"(c[2]), "+f"(c[3])
        : "r"(a[0]), "r"(a[1]), "r"(a[2]), "r"(a[3]), "r"(b0), "r"(b1));
}
__device__ __forceinline__ float ex2(float x) {
    float y;
    asm("ex2.approx.f32 %0, %1;" : "=f"(y) : "f"(x));
    return y;
}

__device__ __forceinline__ uint32_t pack_h2(float x, float y) {
    __half2 p = __floats2half2_rn(x, y);
    return *(uint32_t*)&p;
}
// fp32 (x,y) -> packed fp16x2 hi & lo
__device__ __forceinline__ void split2h(float x, float y, uint32_t& hi, uint32_t& lo) {
    __half hx = __float2half_rn(x), hy = __float2half_rn(y);
    __half2 hp; hp.x = hx; hp.y = hy;
    hi = *(uint32_t*)&hp;
    __half lx = __float2half_rn(x - __half2float(hx));
    __half ly = __float2half_rn(y - __half2float(hy));
    __half2 lp; lp.x = lx; lp.y = ly;
    lo = *(uint32_t*)&lp;
}

// ---------------------------------------------------------------------------
// conv_all: X -> single fp16; W -> fp16 hi/lo. 4 float4 per thread (MLP=4).
// ---------------------------------------------------------------------------
#define XBLK2 1024
#define WBLK2 64
#define CONVG (3 * XBLK2 + 4 * WBLK2)

__global__ __launch_bounds__(256) void conv_all(
    const float* __restrict__ xq, const float* __restrict__ xk,
    const float* __restrict__ xv,
    const float* __restrict__ wq, const float* __restrict__ wk,
    const float* __restrict__ wv, const float* __restrict__ wo)
{
    const int bx = blockIdx.x;
    if (bx < 3 * XBLK2) {
        int job = bx / XBLK2;
        int off = bx - job * XBLK2;
        const float* src = job == 0 ? xq : job == 1 ? xk : xv;
        __half* d = g_x3 + (size_t)job * XN;
        const int i0 = off * 1024 + threadIdx.x;
        float4 v[4];
#pragma unroll
        for (int it = 0; it < 4; it++) v[it] = ((const float4*)src)[i0 + it * 256];
#pragma unroll
        for (int it = 0; it < 4; it++)
            ((uint2*)d)[i0 + it * 256] =
                make_uint2(pack_h2(v[it].x, v[it].y), pack_h2(v[it].z, v[it].w));
    } else {
        int job = (bx - 3 * XBLK2) / WBLK2;
        int off = (bx - 3 * XBLK2) - job * WBLK2;
        const float* src = job == 0 ? wq : job == 1 ? wk : job == 2 ? wv : wo;
        __half* dh = g_w4h + (size_t)job * WN;
        __half* dl = g_w4l + (size_t)job * WN;
        const int i0 = off * 1024 + threadIdx.x;
        float4 v[4];
#pragma unroll
        for (int it = 0; it < 4; it++) v[it] = ((const float4*)src)[i0 + it * 256];
#pragma unroll
        for (int it = 0; it < 4; it++) {
            uint32_t h0, l0, h1, l1;
            split2h(v[it].x, v[it].y, h0, l0);
            split2h(v[it].z, v[it].w, h1, l1);
            ((uint2*)dh)[i0 + it * 256] = make_uint2(h0, h1);
            ((uint2*)dl)[i0 + it * 256] = make_uint2(l0, l1);
        }
    }
}

// ---------------------------------------------------------------------------
// HMMA GEMM (identical to R13 — at mma.sync roofline).
// X single fp16, W fp16 hi/lo -> 2-MMA split. Tile 128x64, BK=64,
// 2-stage cp.async, 256 thr, 2 CTAs/SM.
// MODE 0: fused QKV (gridDim.z=3) -> fp16 head-major. MODE 1: out proj fp32.
// ---------------------------------------------------------------------------
#define GST 32768u
#define GSMEM (2u * GST + 1024u)

template <int MODE>
__global__ __launch_bounds__(256, 2) void gemm_hmma(
    const float* __restrict__ bias0, const float* __restrict__ bias1,
    const float* __restrict__ bias2, float* __restrict__ of)
{
    extern __shared__ char smraw[];
    uint32_t sb0 = smem_u32(smraw);
    uint32_t sb = (sb0 + 1023u) & ~1023u;

    const int tid = threadIdx.x;
    const int l = tid & 31, w = tid >> 5;
    const int wm = w >> 2, wn = w & 3;
    const int c0 = blockIdx.x * 64, m0 = blockIdx.y * 128;
    const int z = (MODE == 0) ? blockIdx.z : 0;

    const __half *Ax, *Bh, *Bl;
    const float* bias;
    float oscale = 1.f;
    __half* o16 = nullptr;
    if (MODE == 0) {
        Ax = g_x3 + (size_t)z * XN;
        Bh = g_w4h + (size_t)z * WN;  Bl = g_w4l + (size_t)z * WN;
        bias = z == 0 ? bias0 : z == 1 ? bias1 : bias2;
        o16 = z == 0 ? g_q16 : z == 1 ? g_k16 : g_v16;
        if (z == 0) oscale = QSCALE;
    } else {
        Ax = g_a16;
        Bh = g_w4h + 3 * WN;  Bl = g_w4l + 3 * WN;
        bias = bias0;
    }

    float acc[4][2][4];
#pragma unroll
    for (int i = 0; i < 4; i++)
#pragma unroll
        for (int j = 0; j < 2; j++)
#pragma unroll
            for (int k = 0; k < 4; k++) acc[i][j][k] = 0.f;

    auto prefetch = [&](int ck, int st) {
        const int k0 = ck * 64;
        const uint32_t sbase = sb + (uint32_t)st * GST;
#pragma unroll
        for (int i = 0; i < 4; i++) {
            int idx = tid + i * 256;
            int r = idx >> 3, c = idx & 7;
            uint32_t off = SW128((uint32_t)(r * 128 + c * 16));
            cp16(sbase + off, Ax + (size_t)(m0 + r) * DMODEL + k0 + c * 8);
        }
#pragma unroll
        for (int i = 0; i < 2; i++) {
            int idx = tid + i * 256;
            int r = idx >> 3, c = idx & 7;
            uint32_t off = SW128((uint32_t)(r * 128 + c * 16));
            cp16(sbase + 16384u + off, Bh + (size_t)(c0 + r) * DMODEL + k0 + c * 8);
            cp16(sbase + 24576u + off, Bl + (size_t)(c0 + r) * DMODEL + k0 + c * 8);
        }
    };

    prefetch(0, 0);
    CP_COMMIT();

    for (int ck = 0; ck < 8; ck++) {
        const int cur = ck & 1;
        if (ck < 7) {
            prefetch(ck + 1, cur ^ 1);
            CP_COMMIT();
            CP_WAIT(1);
        } else {
            CP_WAIT(0);
        }
        __syncthreads();

        const uint32_t stA = sb + (uint32_t)cur * GST;
        const uint32_t stB = stA + 16384u;
#pragma unroll
        for (int ks = 0; ks < 4; ks++) {
            uint32_t ax[4][4], bh4[4], bl4[4];
            const int arow = (l & 7) + ((l >> 3) & 1) * 8;
            const int ac16 = ks * 2 + (l >> 4);
#pragma unroll
            for (int mt = 0; mt < 4; mt++) {
                uint32_t aoff = SW128((uint32_t)((wm * 64 + mt * 16 + arow) * 128 + ac16 * 16));
                ldsm4(ax[mt], stA + aoff);
            }
            const int brow = (l & 7) + ((l >> 4) << 3);
            const int bc16 = ks * 2 + ((l >> 3) & 1);
            uint32_t boff = SW128((uint32_t)((wn * 16 + brow) * 128 + bc16 * 16));
            ldsm4(bh4, stB + boff);
            ldsm4(bl4, stB + 8192u + boff);
#pragma unroll
            for (int mt = 0; mt < 4; mt++) {
                mma_f16(acc[mt][0], ax[mt], bh4[0], bh4[1]);
                mma_f16(acc[mt][1], ax[mt], bh4[2], bh4[3]);
                mma_f16(acc[mt][0], ax[mt], bl4[0], bl4[1]);
                mma_f16(acc[mt][1], ax[mt], bl4[2], bl4[3]);
            }
        }
        __syncthreads();
    }

    // Epilogue
#pragma unroll
    for (int mt = 0; mt < 4; mt++) {
#pragma unroll
        for (int half = 0; half < 2; half++) {
            const int m = m0 + wm * 64 + mt * 16 + (l >> 2) + half * 8;
#pragma unroll
            for (int nt = 0; nt < 2; nt++) {
                const int col = c0 + wn * 16 + nt * 8 + (l & 3) * 2;
                float2 bv = *(const float2*)(bias + col);
                float v0 = acc[mt][nt][half * 2 + 0] + bv.x;
                float v1 = acc[mt][nt][half * 2 + 1] + bv.y;
                if (MODE == 0) {
                    int b = m >> 12, n = m & 4095, h = col >> 6, d = col & 63;
                    size_t a = ((size_t)(b * 8 + h) * 4096 + n) * 64 + d;
                    *(uint32_t*)(o16 + a) = pack_h2(v0 * oscale, v1 * oscale);
                } else {
                    *(float2*)(of + (size_t)m * DMODEL + col) = make_float2(v0, v1);
                }
            }
        }
    }
}

// ---------------------------------------------------------------------------
// Flash attention: CTA = 128 q-rows, 4 warps x 32 q-rows (2 m-blocks) —
// each K/V fragment feeds both m-blocks (halves ldsm redundancy; smem-BW
// was the measured binding pipe at 154us). 3 CTAs/SM (12 warps/SM) restores
// latency hiding that R12's 2 CTAs/SM lacked. Single-barrier 3-stage pipe.
// ---------------------------------------------------------------------------
#define FSTG 16384u
#define FSMEM (3u * FSTG + 1024u)

__global__ __launch_bounds__(128, 3) void flash_hmma()
{
    extern __shared__ char smraw[];
    uint32_t sb0 = smem_u32(smraw);
    uint32_t sb = (sb0 + 1023u) & ~1023u;

    const int tid = threadIdx.x;
    const int l = tid & 31, w = tid >> 5;
    const int bh = blockIdx.y, q0 = blockIdx.x * 128;
    const int b = bh >> 3, h = bh & 7;

    const __half* qg = g_q16 + ((size_t)bh * NQ + q0) * 64;
    const __half* kg = g_k16 + (size_t)bh * NK * 64;
    const __half* vg = g_v16 + (size_t)bh * NK * 64;

    // ---- Q prologue: 128 rows staged through stage0+stage1 (16KB) ----
#pragma unroll
    for (int i = 0; i < 8; i++) {
        int idx = tid + i * 128;               // 0..1023 : 128 rows x 8 chunks
        int r = idx >> 3, c = idx & 7;
        uint32_t off = SW128((uint32_t)(r * 128 + c * 16));
        cp16(sb + off, qg + (size_t)r * 64 + c * 8);
    }
    CP_COMMIT();
    CP_WAIT(0);
    __syncthreads();

    uint32_t qf[2][4][4];
#pragma unroll
    for (int mt = 0; mt < 2; mt++) {
        const int arow = w * 32 + mt * 16 + (l & 7) + ((l >> 3) & 1) * 8;
#pragma unroll
        for (int ks = 0; ks < 4; ks++) {
            uint32_t off = SW128((uint32_t)(arow * 128 + (ks * 2 + (l >> 4)) * 16));
            ldsm4(qf[mt][ks], sb + off);
        }
    }
    __syncthreads();

    float o[2][8][4];
#pragma unroll
    for (int mt = 0; mt < 2; mt++)
#pragma unroll
        for (int i = 0; i < 8; i++)
#pragma unroll
            for (int j = 0; j < 4; j++) o[mt][i][j] = 0.f;
    float osum[2][4];
#pragma unroll
    for (int mt = 0; mt < 2; mt++)
#pragma unroll
        for (int j = 0; j < 4; j++) osum[mt][j] = 0.f;

    auto prefetch = [&](int t, int st) {
        const int kt = t * 64;
        const uint32_t sbase = sb + (uint32_t)st * FSTG;
#pragma unroll
        for (int i = 0; i < 4; i++) {
            int idx = tid + i * 128;
            int r = idx >> 3, c = idx & 7;
            uint32_t off = SW128((uint32_t)(r * 128 + c * 16));
            size_t gsrc = (size_t)(kt + r) * 64 + c * 8;
            cp16(sbase + off,         kg + gsrc);
            cp16(sbase + 8192u + off, vg + gsrc);
        }
    };

    prefetch(0, 0);
    CP_COMMIT();
    prefetch(1, 1);
    CP_COMMIT();

    const int brow = (l & 7) + ((l >> 4) << 3);
    const int vrow_b = (l & 7) + ((l >> 3) & 1) * 8;
    const int bsel = (l >> 3) & 1;
    const int vsel = l >> 4;

    for (int t = 0; t < 64; t++) {
        if (t + 2 < 64) { CP_WAIT(1); } else { CP_WAIT(0); }
        __syncthreads();                         // stage t ready; t-1 consumed
        if (t + 2 < 64) {
            prefetch(t + 2, (t + 2) % 3);        // overwrites slot (t-1)%3
            CP_COMMIT();
        }

        const uint32_t stK = sb + (uint32_t)(t % 3) * FSTG;
        const uint32_t stV = stK + 8192u;

        // ---- S' = Q' K^T : each kf feeds both m-blocks ----
        float s[2][8][4];
#pragma unroll
        for (int mt = 0; mt < 2; mt++)
#pragma unroll
            for (int i = 0; i < 8; i++)
#pragma unroll
                for (int j = 0; j < 4; j++) s[mt][i][j] = 0.f;
#pragma unroll
        for (int ks = 0; ks < 4; ks++) {
            const int bc16 = ks * 2 + bsel;
#pragma unroll
            for (int g = 0; g < 4; g++) {
                uint32_t kf[4];
                uint32_t off = SW128((uint32_t)((g * 16 + brow) * 128 + bc16 * 16));
                ldsm4(kf, stK + off);
#pragma unroll
                for (int mt = 0; mt < 2; mt++) {
                    mma_f16(s[mt][2 * g],     qf[mt][ks], kf[0], kf[1]);
                    mma_f16(s[mt][2 * g + 1], qf[mt][ks], kf[2], kf[3]);
                }
            }
        }

        // ---- p = 2^s' via f32 EX2, pack fp16 fragments per m-block ----
        uint32_t pf[2][4][4];
#pragma unroll
        for (int mt = 0; mt < 2; mt++) {
#pragma unroll
            for (int nt = 0; nt < 8; nt++)
#pragma unroll
                for (int i = 0; i < 4; i++) s[mt][nt][i] = ex2(s[mt][nt][i]);
#pragma unroll
            for (int kk = 0; kk < 4; kk++) {
                pf[mt][kk][0] = pack_h2(s[mt][2 * kk][0],     s[mt][2 * kk][1]);
                pf[mt][kk][1] = pack_h2(s[mt][2 * kk][2],     s[mt][2 * kk][3]);
                pf[mt][kk][2] = pack_h2(s[mt][2 * kk + 1][0], s[mt][2 * kk + 1][1]);
                pf[mt][kk][3] = pack_h2(s[mt][2 * kk + 1][2], s[mt][2 * kk + 1][3]);
            }
        }

        // ---- row sums via P x ones (tensor) ----
#pragma unroll
        for (int mt = 0; mt < 2; mt++)
#pragma unroll
            for (int kk = 0; kk < 4; kk++)
                mma_f16(osum[mt], pf[mt][kk], ONESH2, ONESH2);

        // ---- O += P V : each vf feeds both m-blocks ----
#pragma unroll
        for (int kk = 0; kk < 4; kk++) {
            const int vrow = kk * 16 + vrow_b;
#pragma unroll
            for (int g = 0; g < 4; g++) {
                uint32_t vf[4];
                uint32_t off = SW128((uint32_t)(vrow * 128 + (g * 2 + vsel) * 16));
                ldsm4t(vf, stV + off);
#pragma unroll
                for (int mt = 0; mt < 2; mt++) {
                    mma_f16(o[mt][2 * g],     pf[mt][kk], vf[0], vf[1]);
                    mma_f16(o[mt][2 * g + 1], pf[mt][kk], vf[2], vf[3]);
                }
            }
        }
    }

    // Normalize; write att as single fp16 [b][n][h*64+d]
#pragma unroll
    for (int mt = 0; mt < 2; mt++) {
        const float inv0 = 1.f / osum[mt][0], inv1 = 1.f / osum[mt][2];
        const int r0 = q0 + w * 32 + mt * 16 + (l >> 2);
        const int r1 = r0 + 8;
#pragma unroll
        for (int nt = 0; nt < 8; nt++) {
            const int col = h * 64 + nt * 8 + (l & 3) * 2;
            size_t a0 = ((size_t)b * NQ + r0) * DMODEL + col;
            size_t a1 = ((size_t)b * NQ + r1) * DMODEL + col;
            *(uint32_t*)(g_a16 + a0) = pack_h2(o[mt][nt][0] * inv0, o[mt][nt][1] * inv0);
            *(uint32_t*)(g_a16 + a1) = pack_h2(o[mt][nt][2] * inv1, o[mt][nt][3] * inv1);
        }
    }
}

// ---------------------------------------------------------------------------
// Launch
// ---------------------------------------------------------------------------
extern "C" void kernel_launch(void* const* d_in, const int* in_sizes, int n_in,
                              void* d_out, int out_size)
{
    const float* queries = (const float*)d_in[0];
    const float* keys    = (const float*)d_in[1];
    const float* values  = (const float*)d_in[2];
    const float* Wq = (const float*)d_in[3];
    const float* bq = (const float*)d_in[4];
    const float* Wk = (const float*)d_in[5];
    const float* bk = (const float*)d_in[6];
    const float* Wv = (const float*)d_in[7];
    const float* bv = (const float*)d_in[8];
    const float* Wo = (const float*)d_in[9];
    const float* bo = (const float*)d_in[10];
    float* out = (float*)d_out;

    cudaFuncSetAttribute(gemm_hmma<0>, cudaFuncAttributeMaxDynamicSharedMemorySize, (int)GSMEM);
    cudaFuncSetAttribute(gemm_hmma<1>, cudaFuncAttributeMaxDynamicSharedMemorySize, (int)GSMEM);
    cudaFuncSetAttribute(flash_hmma, cudaFuncAttributeMaxDynamicSharedMemorySize, (int)FSMEM);

    conv_all<<<CONVG, 256>>>(queries, keys, values, Wq, Wk, Wv, Wo);

    gemm_hmma<0><<<dim3(8, 64, 3), 256, GSMEM>>>(bq, bk, bv, nullptr);

    flash_hmma<<<dim3(NQ / 128, BHX), 128, FSMEM>>>();

    gemm_hmma<1><<<dim3(8, 64), 256, GSMEM>>>(bo, nullptr, nullptr, out);
}

// round 15
// speedup vs baseline: 1.0655x; 1.0655x over previous
#include <cuda_runtime.h>
#include <cuda_bf16.h>
#include <cuda_fp16.h>
#include <math.h>
#include <stdint.h>

#define BATCH 2
#define HEADS 8
#define NQ 4096
#define NK 4096
#define DMODEL 512
#define DHEAD 64
#define BHX (BATCH * HEADS)
#define MROWS (BATCH * NQ)

#define XN ((size_t)MROWS * DMODEL)
#define WN ((size_t)DMODEL * DMODEL)

// log2(e)/8 folded into Q so p = 2^(q'.k)
#define QSCALE 0.18033688011112042f
#define ONESH2 0x3C003C00u             // fp16x2 {1,1}

// ---------------------------------------------------------------------------
// Scratch (__device__ globals)
// ---------------------------------------------------------------------------
__device__ __half g_q16[(size_t)BHX * NQ * DHEAD];
__device__ __half g_k16[(size_t)BHX * NK * DHEAD];
__device__ __half g_v16[(size_t)BHX * NK * DHEAD];
__device__ __half g_x3[3 * XN];        // X inputs, single fp16
__device__ __half g_w4h[4 * WN];       // W fp16 hi
__device__ __half g_w4l[4 * WN];       // W fp16 lo
__device__ __half g_a16[XN];           // att, single fp16

// ---------------------------------------------------------------------------
// PTX helpers
// ---------------------------------------------------------------------------
__device__ __forceinline__ uint32_t smem_u32(const void* p) {
    uint32_t a;
    asm("{ .reg .u64 t; cvta.to.shared.u64 t, %1; cvt.u32.u64 %0, t; }"
        : "=r"(a) : "l"(p));
    return a;
}
#define SW128(o) ((o) ^ (((o) >> 3) & 0x70))

__device__ __forceinline__ void cp16(uint32_t dst, const void* src) {
    asm volatile("cp.async.cg.shared.global [%0], [%1], 16;"
                 :: "r"(dst), "l"(src) : "memory");
}
#define CP_COMMIT() asm volatile("cp.async.commit_group;" ::: "memory")
#define CP_WAIT(N)  asm volatile("cp.async.wait_group %0;" :: "n"(N) : "memory")

__device__ __forceinline__ void ldsm4(uint32_t* r, uint32_t a) {
    asm volatile("ldmatrix.sync.aligned.m8n8.x4.shared.b16 {%0,%1,%2,%3}, [%4];"
                 : "=r"(r[0]), "=r"(r[1]), "=r"(r[2]), "=r"(r[3]) : "r"(a));
}
__device__ __forceinline__ void ldsm4t(uint32_t* r, uint32_t a) {
    asm volatile("ldmatrix.sync.aligned.m8n8.x4.trans.shared.b16 {%0,%1,%2,%3}, [%4];"
                 : "=r"(r[0]), "=r"(r[1]), "=r"(r[2]), "=r"(r[3]) : "r"(a));
}
__device__ __forceinline__ void mma_f16(float* c, const uint32_t* a,
                                        uint32_t b0, uint32_t b1) {
    asm volatile(
        "mma.sync.aligned.m16n8k16.row.col.f32.f16.f16.f32 "
        "{%0,%1,%2,%3}, {%4,%5,%6,%7}, {%8,%9}, {%0,%1,%2,%3};"
        : "+f"(c[0]), "+f"(c[1]), "+f"(c[2]), "+f"(c[3])
        : "r"(a[0]), "r"(a[1]), "r"(a[2]), "r"(a[3]), "r"(b0), "r"(b1));
}
__device__ __forceinline__ float ex2(float x) {
    float y;
    asm("ex2.approx.f32 %0, %1;" : "=f"(y) : "f"(x));
    return y;
}

__device__ __forceinline__ uint32_t pack_h2(float x, float y) {
    __half2 p = __floats2half2_rn(x, y);
    return *(uint32_t*)&p;
}
// fp32 (x,y) -> packed fp16x2 hi & lo
__device__ __forceinline__ void split2h(float x, float y, uint32_t& hi, uint32_t& lo) {
    __half hx = __float2half_rn(x), hy = __float2half_rn(y);
    __half2 hp; hp.x = hx; hp.y = hy;
    hi = *(uint32_t*)&hp;
    __half lx = __float2half_rn(x - __half2float(hx));
    __half ly = __float2half_rn(y - __half2float(hy));
    __half2 lp; lp.x = lx; lp.y = ly;
    lo = *(uint32_t*)&lp;
}

// ---------------------------------------------------------------------------
// conv_all: X -> single fp16; W -> fp16 hi/lo. 4 float4 per thread (MLP=4).
// ---------------------------------------------------------------------------
#define XBLK2 1024
#define WBLK2 64
#define CONVG (3 * XBLK2 + 4 * WBLK2)

__global__ __launch_bounds__(256) void conv_all(
    const float* __restrict__ xq, const float* __restrict__ xk,
    const float* __restrict__ xv,
    const float* __restrict__ wq, const float* __restrict__ wk,
    const float* __restrict__ wv, const float* __restrict__ wo)
{
    const int bx = blockIdx.x;
    if (bx < 3 * XBLK2) {
        int job = bx / XBLK2;
        int off = bx - job * XBLK2;
        const float* src = job == 0 ? xq : job == 1 ? xk : xv;
        __half* d = g_x3 + (size_t)job * XN;
        const int i0 = off * 1024 + threadIdx.x;
        float4 v[4];
#pragma unroll
        for (int it = 0; it < 4; it++) v[it] = ((const float4*)src)[i0 + it * 256];
#pragma unroll
        for (int it = 0; it < 4; it++)
            ((uint2*)d)[i0 + it * 256] =
                make_uint2(pack_h2(v[it].x, v[it].y), pack_h2(v[it].z, v[it].w));
    } else {
        int job = (bx - 3 * XBLK2) / WBLK2;
        int off = (bx - 3 * XBLK2) - job * WBLK2;
        const float* src = job == 0 ? wq : job == 1 ? wk : job == 2 ? wv : wo;
        __half* dh = g_w4h + (size_t)job * WN;
        __half* dl = g_w4l + (size_t)job * WN;
        const int i0 = off * 1024 + threadIdx.x;
        float4 v[4];
#pragma unroll
        for (int it = 0; it < 4; it++) v[it] = ((const float4*)src)[i0 + it * 256];
#pragma unroll
        for (int it = 0; it < 4; it++) {
            uint32_t h0, l0, h1, l1;
            split2h(v[it].x, v[it].y, h0, l0);
            split2h(v[it].z, v[it].w, h1, l1);
            ((uint2*)dh)[i0 + it * 256] = make_uint2(h0, h1);
            ((uint2*)dl)[i0 + it * 256] = make_uint2(l0, l1);
        }
    }
}

// ---------------------------------------------------------------------------
// HMMA GEMM: X single fp16, W fp16 hi/lo -> 2-MMA split.
// Tile 128x64, BK=64, 2-stage cp.async, 256 thr, 2 CTAs/SM.
// Inner ks-iteration restructured into two 8-MMA passes (hi then lo) so the
// accumulator RAW gap grows from 2 issues to 8 (>> HMMA latency).
// MODE 0: fused QKV (gridDim.z=3) -> fp16 head-major. MODE 1: out proj fp32.
// ---------------------------------------------------------------------------
#define GST 32768u
#define GSMEM (2u * GST + 1024u)

template <int MODE>
__global__ __launch_bounds__(256, 2) void gemm_hmma(
    const float* __restrict__ bias0, const float* __restrict__ bias1,
    const float* __restrict__ bias2, float* __restrict__ of)
{
    extern __shared__ char smraw[];
    uint32_t sb0 = smem_u32(smraw);
    uint32_t sb = (sb0 + 1023u) & ~1023u;

    const int tid = threadIdx.x;
    const int l = tid & 31, w = tid >> 5;
    const int wm = w >> 2, wn = w & 3;
    const int c0 = blockIdx.x * 64, m0 = blockIdx.y * 128;
    const int z = (MODE == 0) ? blockIdx.z : 0;

    const __half *Ax, *Bh, *Bl;
    const float* bias;
    float oscale = 1.f;
    __half* o16 = nullptr;
    if (MODE == 0) {
        Ax = g_x3 + (size_t)z * XN;
        Bh = g_w4h + (size_t)z * WN;  Bl = g_w4l + (size_t)z * WN;
        bias = z == 0 ? bias0 : z == 1 ? bias1 : bias2;
        o16 = z == 0 ? g_q16 : z == 1 ? g_k16 : g_v16;
        if (z == 0) oscale = QSCALE;
    } else {
        Ax = g_a16;
        Bh = g_w4h + 3 * WN;  Bl = g_w4l + 3 * WN;
        bias = bias0;
    }

    float acc[4][2][4];
#pragma unroll
    for (int i = 0; i < 4; i++)
#pragma unroll
        for (int j = 0; j < 2; j++)
#pragma unroll
            for (int k = 0; k < 4; k++) acc[i][j][k] = 0.f;

    auto prefetch = [&](int ck, int st) {
        const int k0 = ck * 64;
        const uint32_t sbase = sb + (uint32_t)st * GST;
#pragma unroll
        for (int i = 0; i < 4; i++) {
            int idx = tid + i * 256;
            int r = idx >> 3, c = idx & 7;
            uint32_t off = SW128((uint32_t)(r * 128 + c * 16));
            cp16(sbase + off, Ax + (size_t)(m0 + r) * DMODEL + k0 + c * 8);
        }
#pragma unroll
        for (int i = 0; i < 2; i++) {
            int idx = tid + i * 256;
            int r = idx >> 3, c = idx & 7;
            uint32_t off = SW128((uint32_t)(r * 128 + c * 16));
            cp16(sbase + 16384u + off, Bh + (size_t)(c0 + r) * DMODEL + k0 + c * 8);
            cp16(sbase + 24576u + off, Bl + (size_t)(c0 + r) * DMODEL + k0 + c * 8);
        }
    };

    prefetch(0, 0);
    CP_COMMIT();

    for (int ck = 0; ck < 8; ck++) {
        const int cur = ck & 1;
        if (ck < 7) {
            prefetch(ck + 1, cur ^ 1);
            CP_COMMIT();
            CP_WAIT(1);
        } else {
            CP_WAIT(0);
        }
        __syncthreads();

        const uint32_t stA = sb + (uint32_t)cur * GST;
        const uint32_t stB = stA + 16384u;
#pragma unroll
        for (int ks = 0; ks < 4; ks++) {
            uint32_t ax[4][4], bh4[4], bl4[4];
            const int arow = (l & 7) + ((l >> 3) & 1) * 8;
            const int ac16 = ks * 2 + (l >> 4);
#pragma unroll
            for (int mt = 0; mt < 4; mt++) {
                uint32_t aoff = SW128((uint32_t)((wm * 64 + mt * 16 + arow) * 128 + ac16 * 16));
                ldsm4(ax[mt], stA + aoff);
            }
            const int brow = (l & 7) + ((l >> 4) << 3);
            const int bc16 = ks * 2 + ((l >> 3) & 1);
            uint32_t boff = SW128((uint32_t)((wn * 16 + brow) * 128 + bc16 * 16));
            ldsm4(bh4, stB + boff);
            ldsm4(bl4, stB + 8192u + boff);
            // pass 1: X x Whi over all accumulators (RAW gap = 8 issues)
#pragma unroll
            for (int mt = 0; mt < 4; mt++) {
                mma_f16(acc[mt][0], ax[mt], bh4[0], bh4[1]);
                mma_f16(acc[mt][1], ax[mt], bh4[2], bh4[3]);
            }
            // pass 2: X x Wlo
#pragma unroll
            for (int mt = 0; mt < 4; mt++) {
                mma_f16(acc[mt][0], ax[mt], bl4[0], bl4[1]);
                mma_f16(acc[mt][1], ax[mt], bl4[2], bl4[3]);
            }
        }
        __syncthreads();
    }

    // Epilogue
#pragma unroll
    for (int mt = 0; mt < 4; mt++) {
#pragma unroll
        for (int half = 0; half < 2; half++) {
            const int m = m0 + wm * 64 + mt * 16 + (l >> 2) + half * 8;
#pragma unroll
            for (int nt = 0; nt < 2; nt++) {
                const int col = c0 + wn * 16 + nt * 8 + (l & 3) * 2;
                float2 bv = *(const float2*)(bias + col);
                float v0 = acc[mt][nt][half * 2 + 0] + bv.x;
                float v1 = acc[mt][nt][half * 2 + 1] + bv.y;
                if (MODE == 0) {
                    int b = m >> 12, n = m & 4095, h = col >> 6, d = col & 63;
                    size_t a = ((size_t)(b * 8 + h) * 4096 + n) * 64 + d;
                    *(uint32_t*)(o16 + a) = pack_h2(v0 * oscale, v1 * oscale);
                } else {
                    *(float2*)(of + (size_t)m * DMODEL + col) = make_float2(v0, v1);
                }
            }
        }
    }
}

// ---------------------------------------------------------------------------
// Flash attention (R13 exactly — best measured config): 4 warps, 64 q-rows/CTA,
// 4 CTAs/SM, 3-stage cp.async, single-barrier pipeline. Q pre-scaled by
// log2e/8; p = 2^s' via f32 EX2; row sums via P x ones MMA; O += P V fp16 MMA.
// ---------------------------------------------------------------------------
#define FSTG 16384u
#define FSMEM (3u * FSTG + 1024u)

__global__ __launch_bounds__(128, 4) void flash_hmma()
{
    extern __shared__ char smraw[];
    uint32_t sb0 = smem_u32(smraw);
    uint32_t sb = (sb0 + 1023u) & ~1023u;

    const int tid = threadIdx.x;
    const int l = tid & 31, w = tid >> 5;
    const int bh = blockIdx.y, q0 = blockIdx.x * 64;
    const int b = bh >> 3, h = bh & 7;

    const __half* qg = g_q16 + ((size_t)bh * NQ + q0) * 64;
    const __half* kg = g_k16 + (size_t)bh * NK * 64;
    const __half* vg = g_v16 + (size_t)bh * NK * 64;

    // ---- Q prologue ----
#pragma unroll
    for (int i = 0; i < 4; i++) {
        int idx = tid + i * 128;
        int r = idx >> 3, c = idx & 7;
        uint32_t off = SW128((uint32_t)(r * 128 + c * 16));
        cp16(sb + off, qg + (size_t)r * 64 + c * 8);
    }
    CP_COMMIT();
    CP_WAIT(0);
    __syncthreads();

    uint32_t qf[4][4];
    {
        const int arow = w * 16 + (l & 7) + ((l >> 3) & 1) * 8;
#pragma unroll
        for (int ks = 0; ks < 4; ks++) {
            uint32_t off = SW128((uint32_t)(arow * 128 + (ks * 2 + (l >> 4)) * 16));
            ldsm4(qf[ks], sb + off);
        }
    }
    __syncthreads();

    float o[8][4];
#pragma unroll
    for (int i = 0; i < 8; i++)
#pragma unroll
        for (int j = 0; j < 4; j++) o[i][j] = 0.f;
    float osum[4] = {0.f, 0.f, 0.f, 0.f};

    auto prefetch = [&](int t, int st) {
        const int kt = t * 64;
        const uint32_t sbase = sb + (uint32_t)st * FSTG;
#pragma unroll
        for (int i = 0; i < 4; i++) {
            int idx = tid + i * 128;
            int r = idx >> 3, c = idx & 7;
            uint32_t off = SW128((uint32_t)(r * 128 + c * 16));
            size_t gsrc = (size_t)(kt + r) * 64 + c * 8;
            cp16(sbase + off,         kg + gsrc);
            cp16(sbase + 8192u + off, vg + gsrc);
        }
    };

    prefetch(0, 0);
    CP_COMMIT();
    prefetch(1, 1);
    CP_COMMIT();

    const int brow = (l & 7) + ((l >> 4) << 3);
    const int vrow_b = (l & 7) + ((l >> 3) & 1) * 8;
    const int bsel = (l >> 3) & 1;
    const int vsel = l >> 4;

    for (int t = 0; t < 64; t++) {
        if (t + 2 < 64) { CP_WAIT(1); } else { CP_WAIT(0); }
        __syncthreads();                         // stage t ready; t-1 consumed
        if (t + 2 < 64) {
            prefetch(t + 2, (t + 2) % 3);        // overwrites slot (t-1)%3
            CP_COMMIT();
        }

        const uint32_t stK = sb + (uint32_t)(t % 3) * FSTG;
        const uint32_t stV = stK + 8192u;

        // ---- S' = Q' K^T ----
        float s[8][4];
#pragma unroll
        for (int i = 0; i < 8; i++)
#pragma unroll
            for (int j = 0; j < 4; j++) s[i][j] = 0.f;
#pragma unroll
        for (int ks = 0; ks < 4; ks++) {
            const int bc16 = ks * 2 + bsel;
#pragma unroll
            for (int g = 0; g < 4; g++) {
                uint32_t kf[4];
                uint32_t off = SW128((uint32_t)((g * 16 + brow) * 128 + bc16 * 16));
                ldsm4(kf, stK + off);
                mma_f16(s[2 * g],     qf[ks], kf[0], kf[1]);
                mma_f16(s[2 * g + 1], qf[ks], kf[2], kf[3]);
            }
        }

        // ---- p = 2^s' via f32 EX2, pack fp16 fragments ----
        uint32_t pf[4][4];
#pragma unroll
        for (int nt = 0; nt < 8; nt++)
#pragma unroll
            for (int i = 0; i < 4; i++) s[nt][i] = ex2(s[nt][i]);
#pragma unroll
        for (int kk = 0; kk < 4; kk++) {
            pf[kk][0] = pack_h2(s[2 * kk][0],     s[2 * kk][1]);
            pf[kk][1] = pack_h2(s[2 * kk][2],     s[2 * kk][3]);
            pf[kk][2] = pack_h2(s[2 * kk + 1][0], s[2 * kk + 1][1]);
            pf[kk][3] = pack_h2(s[2 * kk + 1][2], s[2 * kk + 1][3]);
        }

        // ---- row sums via P x ones (tensor) ----
#pragma unroll
        for (int kk = 0; kk < 4; kk++)
            mma_f16(osum, pf[kk], ONESH2, ONESH2);

        // ---- O += P V ----
#pragma unroll
        for (int kk = 0; kk < 4; kk++) {
            const int vrow = kk * 16 + vrow_b;
#pragma unroll
            for (int g = 0; g < 4; g++) {
                uint32_t vf[4];
                uint32_t off = SW128((uint32_t)(vrow * 128 + (g * 2 + vsel) * 16));
                ldsm4t(vf, stV + off);
                mma_f16(o[2 * g],     pf[kk], vf[0], vf[1]);
                mma_f16(o[2 * g + 1], pf[kk], vf[2], vf[3]);
            }
        }
    }

    // Normalize; write att as single fp16 [b][n][h*64+d]
    const float inv0 = 1.f / osum[0], inv1 = 1.f / osum[2];
    const int r0 = q0 + w * 16 + (l >> 2);
    const int r1 = r0 + 8;
#pragma unroll
    for (int nt = 0; nt < 8; nt++) {
        const int col = h * 64 + nt * 8 + (l & 3) * 2;
        size_t a0 = ((size_t)b * NQ + r0) * DMODEL + col;
        size_t a1 = ((size_t)b * NQ + r1) * DMODEL + col;
        *(uint32_t*)(g_a16 + a0) = pack_h2(o[nt][0] * inv0, o[nt][1] * inv0);
        *(uint32_t*)(g_a16 + a1) = pack_h2(o[nt][2] * inv1, o[nt][3] * inv1);
    }
}

// ---------------------------------------------------------------------------
// Launch
// ---------------------------------------------------------------------------
extern "C" void kernel_launch(void* const* d_in, const int* in_sizes, int n_in,
                              void* d_out, int out_size)
{
    const float* queries = (const float*)d_in[0];
    const float* keys    = (const float*)d_in[1];
    const float* values  = (const float*)d_in[2];
    const float* Wq = (const float*)d_in[3];
    const float* bq = (const float*)d_in[4];
    const float* Wk = (const float*)d_in[5];
    const float* bk = (const float*)d_in[6];
    const float* Wv = (const float*)d_in[7];
    const float* bv = (const float*)d_in[8];
    const float* Wo = (const float*)d_in[9];
    const float* bo = (const float*)d_in[10];
    float* out = (float*)d_out;

    cudaFuncSetAttribute(gemm_hmma<0>, cudaFuncAttributeMaxDynamicSharedMemorySize, (int)GSMEM);
    cudaFuncSetAttribute(gemm_hmma<1>, cudaFuncAttributeMaxDynamicSharedMemorySize, (int)GSMEM);
    cudaFuncSetAttribute(flash_hmma, cudaFuncAttributeMaxDynamicSharedMemorySize, (int)FSMEM);

    conv_all<<<CONVG, 256>>>(queries, keys, values, Wq, Wk, Wv, Wo);

    gemm_hmma<0><<<dim3(8, 64, 3), 256, GSMEM>>>(bq, bk, bv, nullptr);

    flash_hmma<<<dim3(NQ / 64, BHX), 128, FSMEM>>>();

    gemm_hmma<1><<<dim3(8, 64), 256, GSMEM>>>(bo, nullptr, nullptr, out);
}

// round 16
// speedup vs baseline: 1.1397x; 1.0696x over previous
#include <cuda_runtime.h>
#include <cuda_bf16.h>
#include <cuda_fp16.h>
#include <math.h>
#include <stdint.h>

#define BATCH 2
#define HEADS 8
#define NQ 4096
#define NK 4096
#define DMODEL 512
#define DHEAD 64
#define BHX (BATCH * HEADS)
#define MROWS (BATCH * NQ)

#define XN ((size_t)MROWS * DMODEL)
#define WN ((size_t)DMODEL * DMODEL)

// log2(e)/8 folded into Q so p = 2^(q'.k)
#define QSCALE 0.18033688011112042f
#define ONESH2 0x3C003C00u             // fp16x2 {1,1}

// ---------------------------------------------------------------------------
// Scratch (__device__ globals)
// ---------------------------------------------------------------------------
__device__ __half g_q16[(size_t)BHX * NQ * DHEAD];
__device__ __half g_k16[(size_t)BHX * NK * DHEAD];
__device__ __half g_v16[(size_t)BHX * NK * DHEAD];
__device__ __half g_x3[3 * XN];        // X inputs, single fp16
__device__ __half g_w4h[4 * WN];       // W fp16 hi
__device__ __half g_w4l[4 * WN];       // W fp16 lo (used only by Wq)
__device__ __half g_a16[XN];           // att, single fp16

// ---------------------------------------------------------------------------
// PTX helpers
// ---------------------------------------------------------------------------
__device__ __forceinline__ uint32_t smem_u32(const void* p) {
    uint32_t a;
    asm("{ .reg .u64 t; cvta.to.shared.u64 t, %1; cvt.u32.u64 %0, t; }"
        : "=r"(a) : "l"(p));
    return a;
}
#define SW128(o) ((o) ^ (((o) >> 3) & 0x70))

__device__ __forceinline__ void cp16(uint32_t dst, const void* src) {
    asm volatile("cp.async.cg.shared.global [%0], [%1], 16;"
                 :: "r"(dst), "l"(src) : "memory");
}
#define CP_COMMIT() asm volatile("cp.async.commit_group;" ::: "memory")
#define CP_WAIT(N)  asm volatile("cp.async.wait_group %0;" :: "n"(N) : "memory")

__device__ __forceinline__ void ldsm4(uint32_t* r, uint32_t a) {
    asm volatile("ldmatrix.sync.aligned.m8n8.x4.shared.b16 {%0,%1,%2,%3}, [%4];"
                 : "=r"(r[0]), "=r"(r[1]), "=r"(r[2]), "=r"(r[3]) : "r"(a));
}
__device__ __forceinline__ void ldsm4t(uint32_t* r, uint32_t a) {
    asm volatile("ldmatrix.sync.aligned.m8n8.x4.trans.shared.b16 {%0,%1,%2,%3}, [%4];"
                 : "=r"(r[0]), "=r"(r[1]), "=r"(r[2]), "=r"(r[3]) : "r"(a));
}
__device__ __forceinline__ void mma_f16(float* c, const uint32_t* a,
                                        uint32_t b0, uint32_t b1) {
    asm volatile(
        "mma.sync.aligned.m16n8k16.row.col.f32.f16.f16.f32 "
        "{%0,%1,%2,%3}, {%4,%5,%6,%7}, {%8,%9}, {%0,%1,%2,%3};"
        : "+f"(c[0]), "+f"(c[1]), "+f"(c[2]), "+f"(c[3])
        : "r"(a[0]), "r"(a[1]), "r"(a[2]), "r"(a[3]), "r"(b0), "r"(b1));
}
__device__ __forceinline__ float ex2(float x) {
    float y;
    asm("ex2.approx.f32 %0, %1;" : "=f"(y) : "f"(x));
    return y;
}

__device__ __forceinline__ uint32_t pack_h2(float x, float y) {
    __half2 p = __floats2half2_rn(x, y);
    return *(uint32_t*)&p;
}
// fp32 (x,y) -> packed fp16x2 hi & lo
__device__ __forceinline__ void split2h(float x, float y, uint32_t& hi, uint32_t& lo) {
    __half hx = __float2half_rn(x), hy = __float2half_rn(y);
    __half2 hp; hp.x = hx; hp.y = hy;
    hi = *(uint32_t*)&hp;
    __half lx = __float2half_rn(x - __half2float(hx));
    __half ly = __float2half_rn(y - __half2float(hy));
    __half2 lp; lp.x = lx; lp.y = ly;
    lo = *(uint32_t*)&lp;
}

// ---------------------------------------------------------------------------
// conv_all: X -> single fp16; W -> fp16 hi/lo. 4 float4 per thread (MLP=4).
// ---------------------------------------------------------------------------
#define XBLK2 1024
#define WBLK2 64
#define CONVG (3 * XBLK2 + 4 * WBLK2)

__global__ __launch_bounds__(256) void conv_all(
    const float* __restrict__ xq, const float* __restrict__ xk,
    const float* __restrict__ xv,
    const float* __restrict__ wq, const float* __restrict__ wk,
    const float* __restrict__ wv, const float* __restrict__ wo)
{
    const int bx = blockIdx.x;
    if (bx < 3 * XBLK2) {
        int job = bx / XBLK2;
        int off = bx - job * XBLK2;
        const float* src = job == 0 ? xq : job == 1 ? xk : xv;
        __half* d = g_x3 + (size_t)job * XN;
        const int i0 = off * 1024 + threadIdx.x;
        float4 v[4];
#pragma unroll
        for (int it = 0; it < 4; it++) v[it] = ((const float4*)src)[i0 + it * 256];
#pragma unroll
        for (int it = 0; it < 4; it++)
            ((uint2*)d)[i0 + it * 256] =
                make_uint2(pack_h2(v[it].x, v[it].y), pack_h2(v[it].z, v[it].w));
    } else {
        int job = (bx - 3 * XBLK2) / WBLK2;
        int off = (bx - 3 * XBLK2) - job * WBLK2;
        const float* src = job == 0 ? wq : job == 1 ? wk : job == 2 ? wv : wo;
        __half* dh = g_w4h + (size_t)job * WN;
        __half* dl = g_w4l + (size_t)job * WN;
        const int i0 = off * 1024 + threadIdx.x;
        float4 v[4];
#pragma unroll
        for (int it = 0; it < 4; it++) v[it] = ((const float4*)src)[i0 + it * 256];
#pragma unroll
        for (int it = 0; it < 4; it++) {
            uint32_t h0, l0, h1, l1;
            split2h(v[it].x, v[it].y, h0, l0);
            split2h(v[it].z, v[it].w, h1, l1);
            ((uint2*)dh)[i0 + it * 256] = make_uint2(h0, h1);
            ((uint2*)dl)[i0 + it * 256] = make_uint2(l0, l1);
        }
    }
}

// ---------------------------------------------------------------------------
// HMMA GEMM: X single fp16 x W fp16. W split selectable at runtime (uniform):
// use_lo=1 -> 2-MMA hi/lo split (Wq); use_lo=0 -> single-MMA (Wk/Wv/Wo).
// Tile 128x64, BK=64, 2-stage cp.async, 256 thr, 2 CTAs/SM.
// MODE 0: fused QKV (gridDim.z=3) -> fp16 head-major. MODE 1: out proj fp32.
// ---------------------------------------------------------------------------
#define GST 32768u
#define GSMEM (2u * GST + 1024u)

template <int MODE>
__global__ __launch_bounds__(256, 2) void gemm_hmma(
    const float* __restrict__ bias0, const float* __restrict__ bias1,
    const float* __restrict__ bias2, float* __restrict__ of)
{
    extern __shared__ char smraw[];
    uint32_t sb0 = smem_u32(smraw);
    uint32_t sb = (sb0 + 1023u) & ~1023u;

    const int tid = threadIdx.x;
    const int l = tid & 31, w = tid >> 5;
    const int wm = w >> 2, wn = w & 3;
    const int c0 = blockIdx.x * 64, m0 = blockIdx.y * 128;
    const int z = (MODE == 0) ? blockIdx.z : 0;

    const __half *Ax, *Bh, *Bl;
    const float* bias;
    float oscale = 1.f;
    __half* o16 = nullptr;
    bool use_lo;
    if (MODE == 0) {
        Ax = g_x3 + (size_t)z * XN;
        Bh = g_w4h + (size_t)z * WN;  Bl = g_w4l + (size_t)z * WN;
        bias = z == 0 ? bias0 : z == 1 ? bias1 : bias2;
        o16 = z == 0 ? g_q16 : z == 1 ? g_k16 : g_v16;
        if (z == 0) oscale = QSCALE;
        use_lo = (z == 0);                 // only Wq keeps the lo split
    } else {
        Ax = g_a16;
        Bh = g_w4h + 3 * WN;  Bl = g_w4l + 3 * WN;
        bias = bias0;
        use_lo = false;                    // Wo single fp16
    }

    float acc[4][2][4];
#pragma unroll
    for (int i = 0; i < 4; i++)
#pragma unroll
        for (int j = 0; j < 2; j++)
#pragma unroll
            for (int k = 0; k < 4; k++) acc[i][j][k] = 0.f;

    auto prefetch = [&](int ck, int st) {
        const int k0 = ck * 64;
        const uint32_t sbase = sb + (uint32_t)st * GST;
#pragma unroll
        for (int i = 0; i < 4; i++) {
            int idx = tid + i * 256;
            int r = idx >> 3, c = idx & 7;
            uint32_t off = SW128((uint32_t)(r * 128 + c * 16));
            cp16(sbase + off, Ax + (size_t)(m0 + r) * DMODEL + k0 + c * 8);
        }
#pragma unroll
        for (int i = 0; i < 2; i++) {
            int idx = tid + i * 256;
            int r = idx >> 3, c = idx & 7;
            uint32_t off = SW128((uint32_t)(r * 128 + c * 16));
            cp16(sbase + 16384u + off, Bh + (size_t)(c0 + r) * DMODEL + k0 + c * 8);
        }
        if (use_lo) {
#pragma unroll
            for (int i = 0; i < 2; i++) {
                int idx = tid + i * 256;
                int r = idx >> 3, c = idx & 7;
                uint32_t off = SW128((uint32_t)(r * 128 + c * 16));
                cp16(sbase + 24576u + off, Bl + (size_t)(c0 + r) * DMODEL + k0 + c * 8);
            }
        }
    };

    prefetch(0, 0);
    CP_COMMIT();

    for (int ck = 0; ck < 8; ck++) {
        const int cur = ck & 1;
        if (ck < 7) {
            prefetch(ck + 1, cur ^ 1);
            CP_COMMIT();
            CP_WAIT(1);
        } else {
            CP_WAIT(0);
        }
        __syncthreads();

        const uint32_t stA = sb + (uint32_t)cur * GST;
        const uint32_t stB = stA + 16384u;
#pragma unroll
        for (int ks = 0; ks < 4; ks++) {
            uint32_t ax[4][4], bh4[4];
            const int arow = (l & 7) + ((l >> 3) & 1) * 8;
            const int ac16 = ks * 2 + (l >> 4);
#pragma unroll
            for (int mt = 0; mt < 4; mt++) {
                uint32_t aoff = SW128((uint32_t)((wm * 64 + mt * 16 + arow) * 128 + ac16 * 16));
                ldsm4(ax[mt], stA + aoff);
            }
            const int brow = (l & 7) + ((l >> 4) << 3);
            const int bc16 = ks * 2 + ((l >> 3) & 1);
            uint32_t boff = SW128((uint32_t)((wn * 16 + brow) * 128 + bc16 * 16));
            ldsm4(bh4, stB + boff);
            // hi pass
#pragma unroll
            for (int mt = 0; mt < 4; mt++) {
                mma_f16(acc[mt][0], ax[mt], bh4[0], bh4[1]);
                mma_f16(acc[mt][1], ax[mt], bh4[2], bh4[3]);
            }
            // lo pass (Wq only)
            if (use_lo) {
                uint32_t bl4[4];
                ldsm4(bl4, stB + 8192u + boff);
#pragma unroll
                for (int mt = 0; mt < 4; mt++) {
                    mma_f16(acc[mt][0], ax[mt], bl4[0], bl4[1]);
                    mma_f16(acc[mt][1], ax[mt], bl4[2], bl4[3]);
                }
            }
        }
        __syncthreads();
    }

    // Epilogue
#pragma unroll
    for (int mt = 0; mt < 4; mt++) {
#pragma unroll
        for (int half = 0; half < 2; half++) {
            const int m = m0 + wm * 64 + mt * 16 + (l >> 2) + half * 8;
#pragma unroll
            for (int nt = 0; nt < 2; nt++) {
                const int col = c0 + wn * 16 + nt * 8 + (l & 3) * 2;
                float2 bv = *(const float2*)(bias + col);
                float v0 = acc[mt][nt][half * 2 + 0] + bv.x;
                float v1 = acc[mt][nt][half * 2 + 1] + bv.y;
                if (MODE == 0) {
                    int b = m >> 12, n = m & 4095, h = col >> 6, d = col & 63;
                    size_t a = ((size_t)(b * 8 + h) * 4096 + n) * 64 + d;
                    *(uint32_t*)(o16 + a) = pack_h2(v0 * oscale, v1 * oscale);
                } else {
                    *(float2*)(of + (size_t)m * DMODEL + col) = make_float2(v0, v1);
                }
            }
        }
    }
}

// ---------------------------------------------------------------------------
// Flash attention (R13/R15 exact — best measured config): 4 warps,
// 64 q-rows/CTA, 4 CTAs/SM, 3-stage cp.async, single-barrier pipeline.
// ---------------------------------------------------------------------------
#define FSTG 16384u
#define FSMEM (3u * FSTG + 1024u)

__global__ __launch_bounds__(128, 4) void flash_hmma()
{
    extern __shared__ char smraw[];
    uint32_t sb0 = smem_u32(smraw);
    uint32_t sb = (sb0 + 1023u) & ~1023u;

    const int tid = threadIdx.x;
    const int l = tid & 31, w = tid >> 5;
    const int bh = blockIdx.y, q0 = blockIdx.x * 64;
    const int b = bh >> 3, h = bh & 7;

    const __half* qg = g_q16 + ((size_t)bh * NQ + q0) * 64;
    const __half* kg = g_k16 + (size_t)bh * NK * 64;
    const __half* vg = g_v16 + (size_t)bh * NK * 64;

    // ---- Q prologue ----
#pragma unroll
    for (int i = 0; i < 4; i++) {
        int idx = tid + i * 128;
        int r = idx >> 3, c = idx & 7;
        uint32_t off = SW128((uint32_t)(r * 128 + c * 16));
        cp16(sb + off, qg + (size_t)r * 64 + c * 8);
    }
    CP_COMMIT();
    CP_WAIT(0);
    __syncthreads();

    uint32_t qf[4][4];
    {
        const int arow = w * 16 + (l & 7) + ((l >> 3) & 1) * 8;
#pragma unroll
        for (int ks = 0; ks < 4; ks++) {
            uint32_t off = SW128((uint32_t)(arow * 128 + (ks * 2 + (l >> 4)) * 16));
            ldsm4(qf[ks], sb + off);
        }
    }
    __syncthreads();

    float o[8][4];
#pragma unroll
    for (int i = 0; i < 8; i++)
#pragma unroll
        for (int j = 0; j < 4; j++) o[i][j] = 0.f;
    float osum[4] = {0.f, 0.f, 0.f, 0.f};

    auto prefetch = [&](int t, int st) {
        const int kt = t * 64;
        const uint32_t sbase = sb + (uint32_t)st * FSTG;
#pragma unroll
        for (int i = 0; i < 4; i++) {
            int idx = tid + i * 128;
            int r = idx >> 3, c = idx & 7;
            uint32_t off = SW128((uint32_t)(r * 128 + c * 16));
            size_t gsrc = (size_t)(kt + r) * 64 + c * 8;
            cp16(sbase + off,         kg + gsrc);
            cp16(sbase + 8192u + off, vg + gsrc);
        }
    };

    prefetch(0, 0);
    CP_COMMIT();
    prefetch(1, 1);
    CP_COMMIT();

    const int brow = (l & 7) + ((l >> 4) << 3);
    const int vrow_b = (l & 7) + ((l >> 3) & 1) * 8;
    const int bsel = (l >> 3) & 1;
    const int vsel = l >> 4;

    for (int t = 0; t < 64; t++) {
        if (t + 2 < 64) { CP_WAIT(1); } else { CP_WAIT(0); }
        __syncthreads();                         // stage t ready; t-1 consumed
        if (t + 2 < 64) {
            prefetch(t + 2, (t + 2) % 3);        // overwrites slot (t-1)%3
            CP_COMMIT();
        }

        const uint32_t stK = sb + (uint32_t)(t % 3) * FSTG;
        const uint32_t stV = stK + 8192u;

        // ---- S' = Q' K^T ----
        float s[8][4];
#pragma unroll
        for (int i = 0; i < 8; i++)
#pragma unroll
            for (int j = 0; j < 4; j++) s[i][j] = 0.f;
#pragma unroll
        for (int ks = 0; ks < 4; ks++) {
            const int bc16 = ks * 2 + bsel;
#pragma unroll
            for (int g = 0; g < 4; g++) {
                uint32_t kf[4];
                uint32_t off = SW128((uint32_t)((g * 16 + brow) * 128 + bc16 * 16));
                ldsm4(kf, stK + off);
                mma_f16(s[2 * g],     qf[ks], kf[0], kf[1]);
                mma_f16(s[2 * g + 1], qf[ks], kf[2], kf[3]);
            }
        }

        // ---- p = 2^s' via f32 EX2, pack fp16 fragments ----
        uint32_t pf[4][4];
#pragma unroll
        for (int nt = 0; nt < 8; nt++)
#pragma unroll
            for (int i = 0; i < 4; i++) s[nt][i] = ex2(s[nt][i]);
#pragma unroll
        for (int kk = 0; kk < 4; kk++) {
            pf[kk][0] = pack_h2(s[2 * kk][0],     s[2 * kk][1]);
            pf[kk][1] = pack_h2(s[2 * kk][2],     s[2 * kk][3]);
            pf[kk][2] = pack_h2(s[2 * kk + 1][0], s[2 * kk + 1][1]);
            pf[kk][3] = pack_h2(s[2 * kk + 1][2], s[2 * kk + 1][3]);
        }

        // ---- row sums via P x ones (tensor) ----
#pragma unroll
        for (int kk = 0; kk < 4; kk++)
            mma_f16(osum, pf[kk], ONESH2, ONESH2);

        // ---- O += P V ----
#pragma unroll
        for (int kk = 0; kk < 4; kk++) {
            const int vrow = kk * 16 + vrow_b;
#pragma unroll
            for (int g = 0; g < 4; g++) {
                uint32_t vf[4];
                uint32_t off = SW128((uint32_t)(vrow * 128 + (g * 2 + vsel) * 16));
                ldsm4t(vf, stV + off);
                mma_f16(o[2 * g],     pf[kk], vf[0], vf[1]);
                mma_f16(o[2 * g + 1], pf[kk], vf[2], vf[3]);
            }
        }
    }

    // Normalize; write att as single fp16 [b][n][h*64+d]
    const float inv0 = 1.f / osum[0], inv1 = 1.f / osum[2];
    const int r0 = q0 + w * 16 + (l >> 2);
    const int r1 = r0 + 8;
#pragma unroll
    for (int nt = 0; nt < 8; nt++) {
        const int col = h * 64 + nt * 8 + (l & 3) * 2;
        size_t a0 = ((size_t)b * NQ + r0) * DMODEL + col;
        size_t a1 = ((size_t)b * NQ + r1) * DMODEL + col;
        *(uint32_t*)(g_a16 + a0) = pack_h2(o[nt][0] * inv0, o[nt][1] * inv0);
        *(uint32_t*)(g_a16 + a1) = pack_h2(o[nt][2] * inv1, o[nt][3] * inv1);
    }
}

// ---------------------------------------------------------------------------
// Launch
// ---------------------------------------------------------------------------
extern "C" void kernel_launch(void* const* d_in, const int* in_sizes, int n_in,
                              void* d_out, int out_size)
{
    const float* queries = (const float*)d_in[0];
    const float* keys    = (const float*)d_in[1];
    const float* values  = (const float*)d_in[2];
    const float* Wq = (const float*)d_in[3];
    const float* bq = (const float*)d_in[4];
    const float* Wk = (const float*)d_in[5];
    const float* bk = (const float*)d_in[6];
    const float* Wv = (const float*)d_in[7];
    const float* bv = (const float*)d_in[8];
    const float* Wo = (const float*)d_in[9];
    const float* bo = (const float*)d_in[10];
    float* out = (float*)d_out;

    cudaFuncSetAttribute(gemm_hmma<0>, cudaFuncAttributeMaxDynamicSharedMemorySize, (int)GSMEM);
    cudaFuncSetAttribute(gemm_hmma<1>, cudaFuncAttributeMaxDynamicSharedMemorySize, (int)GSMEM);
    cudaFuncSetAttribute(flash_hmma, cudaFuncAttributeMaxDynamicSharedMemorySize, (int)FSMEM);

    conv_all<<<CONVG, 256>>>(queries, keys, values, Wq, Wk, Wv, Wo);

    gemm_hmma<0><<<dim3(8, 64, 3), 256, GSMEM>>>(bq, bk, bv, nullptr);

    flash_hmma<<<dim3(NQ / 64, BHX), 128, FSMEM>>>();

    gemm_hmma<1><<<dim3(8, 64), 256, GSMEM>>>(bo, nullptr, nullptr, out);
}